// round 1
// baseline (speedup 1.0000x reference)
#include <cuda_runtime.h>
#include <math.h>
#include <stdint.h>

#define BATCH   32
#define SQ      512
#define DM      512
#define DFF     2048
#define NH      8
#define HD      64
#define TOKENS  (BATCH * SQ)   // 16384

// ---------------- scratch (device globals; no runtime allocation) ----------
__device__ float g_Q  [TOKENS * DM];
__device__ float g_K  [TOKENS * DM];
__device__ float g_V  [TOKENS * DM];
__device__ float g_Ctx[TOKENS * DM];
__device__ float g_T1 [TOKENS * DM];
__device__ float g_A  [TOKENS * DM];
__device__ float g_H  [TOKENS * DFF];
__device__ float g_T2 [TOKENS * DM];

// ---------------- tiled SGEMM: C = A[MxK] @ B[KxN] + bias (+epilogue) ------
// EPI: 0 = bias only, 1 = bias + exact GELU, 2 = bias + residual
#define BM 128
#define BN 128
#define BK 8

__device__ __forceinline__ float gelu_exact(float v) {
    return 0.5f * v * (1.0f + erff(v * 0.70710678118654752f));
}

template <int EPI>
__global__ __launch_bounds__(256) void sgemm_kernel(
    const float* __restrict__ A, const float* __restrict__ B,
    const float* __restrict__ bias, const float* __restrict__ res,
    float* __restrict__ C, int M, int N, int K)
{
    __shared__ float As[BK][132];   // padded: conflict-free transposed stores
    __shared__ float Bs[BK][BN];

    const int tid  = threadIdx.x;
    const int row0 = blockIdx.y * BM;
    const int col0 = blockIdx.x * BN;

    // A loader: thread -> A[row0 + tid/2][(tid&1)*4 .. +3]
    const int a_r = tid >> 1;
    const int a_c = (tid & 1) << 2;
    // B loader: thread -> B[tid/32][col0 + (tid&31)*4 .. +3]
    const int b_r = tid >> 5;
    const int b_c = (tid & 31) << 2;

    const int tx = tid & 15;   // owns cols {tx + 16*j}
    const int ty = tid >> 4;   // owns rows {ty + 16*i}

    float acc[8][8];
    #pragma unroll
    for (int i = 0; i < 8; i++)
        #pragma unroll
        for (int j = 0; j < 8; j++) acc[i][j] = 0.f;

    const float* Aptr = A + (size_t)(row0 + a_r) * K + a_c;
    const float* Bptr = B + (size_t)b_r * N + col0 + b_c;

    for (int k0 = 0; k0 < K; k0 += BK) {
        float4 av = *(const float4*)(Aptr + k0);
        As[a_c + 0][a_r] = av.x;
        As[a_c + 1][a_r] = av.y;
        As[a_c + 2][a_r] = av.z;
        As[a_c + 3][a_r] = av.w;
        float4 bv = *(const float4*)(Bptr + (size_t)k0 * N);
        *(float4*)&Bs[b_r][b_c] = bv;
        __syncthreads();

        #pragma unroll
        for (int k = 0; k < BK; k++) {
            float ra[8], rb[8];
            #pragma unroll
            for (int i = 0; i < 8; i++) ra[i] = As[k][i * 16 + ty];
            #pragma unroll
            for (int j = 0; j < 8; j++) rb[j] = Bs[k][j * 16 + tx];
            #pragma unroll
            for (int i = 0; i < 8; i++)
                #pragma unroll
                for (int j = 0; j < 8; j++)
                    acc[i][j] += ra[i] * rb[j];
        }
        __syncthreads();
    }

    #pragma unroll
    for (int i = 0; i < 8; i++) {
        const int r = row0 + i * 16 + ty;
        #pragma unroll
        for (int j = 0; j < 8; j++) {
            const int c = col0 + j * 16 + tx;
            float v = acc[i][j] + bias[c];
            if (EPI == 1) v = gelu_exact(v);
            if (EPI == 2) v += res[(size_t)r * N + c];
            C[(size_t)r * N + c] = v;
        }
    }
}

// ---------------- flash attention ------------------------------------------
// grid (SQ/64, NH, BATCH), 256 threads. 4 threads per query (sub = lane&3),
// keys interleaved j = jj*4 + sub. smem pitch 65 -> conflict-free.
__global__ __launch_bounds__(256, 2) void attn_kernel(
    const float* __restrict__ Qg, const float* __restrict__ Kg,
    const float* __restrict__ Vg, const float* __restrict__ mask,
    float* __restrict__ O)
{
    extern __shared__ float sm[];
    float* Qs = sm;               // [64][65]
    float* Ks = sm + 64 * 65;     // [64][65]
    float* Vs = sm + 2 * 64 * 65; // [64][65]

    const int t  = threadIdx.x;
    const int q0 = blockIdx.x * 64;
    const int h  = blockIdx.y;
    const int b  = blockIdx.z;

    const int lr = t >> 2;          // loader row 0..63
    const int lc = (t & 3) * 16;    // loader col start
    const size_t base = (size_t)b * SQ * DM + (size_t)h * HD;

    // load + pre-scale Q tile (1/sqrt(64) = 0.125)
    {
        const float* src = Qg + base + (size_t)(q0 + lr) * DM + lc;
        #pragma unroll
        for (int i = 0; i < 16; i += 4) {
            float4 v = *(const float4*)(src + i);
            Qs[lr * 65 + lc + i + 0] = v.x * 0.125f;
            Qs[lr * 65 + lc + i + 1] = v.y * 0.125f;
            Qs[lr * 65 + lc + i + 2] = v.z * 0.125f;
            Qs[lr * 65 + lc + i + 3] = v.w * 0.125f;
        }
    }

    const int qi  = t >> 2;
    const int sub = t & 3;

    float m = -1e30f, l = 0.f;
    float acc[64];
    #pragma unroll
    for (int d = 0; d < 64; d++) acc[d] = 0.f;

    for (int kt = 0; kt < SQ; kt += 64) {
        __syncthreads();   // Q ready (iter 0); K/V consumers done (iter>0)
        {
            const float* ksrc = Kg + base + (size_t)(kt + lr) * DM + lc;
            const float* vsrc = Vg + base + (size_t)(kt + lr) * DM + lc;
            #pragma unroll
            for (int i = 0; i < 16; i += 4) {
                float4 kv = *(const float4*)(ksrc + i);
                Ks[lr * 65 + lc + i + 0] = kv.x;
                Ks[lr * 65 + lc + i + 1] = kv.y;
                Ks[lr * 65 + lc + i + 2] = kv.z;
                Ks[lr * 65 + lc + i + 3] = kv.w;
                float4 vv = *(const float4*)(vsrc + i);
                Vs[lr * 65 + lc + i + 0] = vv.x;
                Vs[lr * 65 + lc + i + 1] = vv.y;
                Vs[lr * 65 + lc + i + 2] = vv.z;
                Vs[lr * 65 + lc + i + 3] = vv.w;
            }
        }
        __syncthreads();

        // scores for this thread's 16 keys
        float s[16];
        #pragma unroll
        for (int jj = 0; jj < 16; jj++) s[jj] = 0.f;
        #pragma unroll
        for (int d = 0; d < 64; d++) {
            const float qv = Qs[qi * 65 + d];
            #pragma unroll
            for (int jj = 0; jj < 16; jj++)
                s[jj] += qv * Ks[(jj * 4 + sub) * 65 + d];
        }
        const float* mrow = mask + ((size_t)b * SQ + (q0 + qi)) * SQ + kt;
        #pragma unroll
        for (int jj = 0; jj < 16; jj++) s[jj] += mrow[jj * 4 + sub];

        // online softmax (group of 4 lanes per query)
        float tmax = s[0];
        #pragma unroll
        for (int jj = 1; jj < 16; jj++) tmax = fmaxf(tmax, s[jj]);
        tmax = fmaxf(tmax, __shfl_xor_sync(0xffffffffu, tmax, 1));
        tmax = fmaxf(tmax, __shfl_xor_sync(0xffffffffu, tmax, 2));
        const float m_new = fmaxf(m, tmax);
        const float scale = __expf(m - m_new);

        float lsum = 0.f;
        #pragma unroll
        for (int jj = 0; jj < 16; jj++) {
            const float p = __expf(s[jj] - m_new);
            s[jj] = p;
            lsum += p;
        }
        lsum += __shfl_xor_sync(0xffffffffu, lsum, 1);
        lsum += __shfl_xor_sync(0xffffffffu, lsum, 2);
        l = l * scale + lsum;
        m = m_new;

        #pragma unroll
        for (int d = 0; d < 64; d++) acc[d] *= scale;
        #pragma unroll
        for (int jj = 0; jj < 16; jj++) {
            const float p = s[jj];
            const float* vrow = &Vs[(jj * 4 + sub) * 65];
            #pragma unroll
            for (int d = 0; d < 64; d++) acc[d] += p * vrow[d];
        }
    }

    // combine partial sums across the 4 lanes of the query group
    #pragma unroll
    for (int d = 0; d < 64; d++) {
        acc[d] += __shfl_xor_sync(0xffffffffu, acc[d], 1);
        acc[d] += __shfl_xor_sync(0xffffffffu, acc[d], 2);
    }
    const float inv_l = 1.f / l;

    float* dst = O + base + (size_t)(q0 + qi) * DM + sub * 16;
    #pragma unroll
    for (int i = 0; i < 16; i += 4) {
        float4 o;
        o.x = acc[sub * 16 + i + 0] * inv_l;
        o.y = acc[sub * 16 + i + 1] * inv_l;
        o.z = acc[sub * 16 + i + 2] * inv_l;
        o.w = acc[sub * 16 + i + 3] * inv_l;
        *(float4*)(dst + i) = o;
    }
}

// ---------------- LayerNorm over last dim (512), one row per block ---------
__global__ __launch_bounds__(256) void ln_kernel(
    const float* __restrict__ X, const float* __restrict__ gam,
    const float* __restrict__ bet, float* __restrict__ O)
{
    __shared__ float s1[8], s2[8];
    const int row = blockIdx.x;
    const int t = threadIdx.x;
    const float* x = X + (size_t)row * DM;
    const float a = x[t];
    const float c = x[t + 256];

    float sum = a + c;
    float sq  = a * a + c * c;
    #pragma unroll
    for (int o = 16; o; o >>= 1) {
        sum += __shfl_xor_sync(0xffffffffu, sum, o);
        sq  += __shfl_xor_sync(0xffffffffu, sq,  o);
    }
    if ((t & 31) == 0) { s1[t >> 5] = sum; s2[t >> 5] = sq; }
    __syncthreads();
    sum = 0.f; sq = 0.f;
    #pragma unroll
    for (int i = 0; i < 8; i++) { sum += s1[i]; sq += s2[i]; }

    const float mu  = sum * (1.0f / DM);
    const float var = sq * (1.0f / DM) - mu * mu;
    const float inv = rsqrtf(var + 1e-12f);

    O[(size_t)row * DM + t]       = (a - mu) * inv * gam[t]       + bet[t];
    O[(size_t)row * DM + t + 256] = (c - mu) * inv * gam[t + 256] + bet[t + 256];
}

// ---------------- launch ----------------------------------------------------
extern "C" void kernel_launch(void* const* d_in, const int* in_sizes, int n_in,
                              void* d_out, int out_size)
{
    const float* x     = (const float*)d_in[0];
    const float* mask  = (const float*)d_in[1];
    const float* Wq    = (const float*)d_in[2];
    const float* bq    = (const float*)d_in[3];
    const float* Wk    = (const float*)d_in[4];
    const float* bk    = (const float*)d_in[5];
    const float* Wv    = (const float*)d_in[6];
    const float* bv    = (const float*)d_in[7];
    const float* Wo    = (const float*)d_in[8];
    const float* bo    = (const float*)d_in[9];
    const float* ln1g  = (const float*)d_in[10];
    const float* ln1b  = (const float*)d_in[11];
    const float* W1    = (const float*)d_in[12];
    const float* b1    = (const float*)d_in[13];
    const float* W2    = (const float*)d_in[14];
    const float* b2    = (const float*)d_in[15];
    const float* ln2g  = (const float*)d_in[16];
    const float* ln2b  = (const float*)d_in[17];
    float* out = (float*)d_out;

    float *Q, *K, *V, *Ctx, *T1, *A, *H, *T2;
    cudaGetSymbolAddress((void**)&Q,   g_Q);
    cudaGetSymbolAddress((void**)&K,   g_K);
    cudaGetSymbolAddress((void**)&V,   g_V);
    cudaGetSymbolAddress((void**)&Ctx, g_Ctx);
    cudaGetSymbolAddress((void**)&T1,  g_T1);
    cudaGetSymbolAddress((void**)&A,   g_A);
    cudaGetSymbolAddress((void**)&H,   g_H);
    cudaGetSymbolAddress((void**)&T2,  g_T2);

    const int attn_smem = 3 * 64 * 65 * (int)sizeof(float);  // 49920 B
    cudaFuncSetAttribute(attn_kernel, cudaFuncAttributeMaxDynamicSharedMemorySize,
                         attn_smem);

    dim3 thr(256);
    dim3 gDM(DM / BN, TOKENS / BM);    // (4, 128)
    dim3 gFF(DFF / BN, TOKENS / BM);   // (16, 128)

    // QKV projections
    sgemm_kernel<0><<<gDM, thr>>>(x, Wq, bq, nullptr, Q, TOKENS, DM, DM);
    sgemm_kernel<0><<<gDM, thr>>>(x, Wk, bk, nullptr, K, TOKENS, DM, DM);
    sgemm_kernel<0><<<gDM, thr>>>(x, Wv, bv, nullptr, V, TOKENS, DM, DM);

    // attention
    attn_kernel<<<dim3(SQ / 64, NH, BATCH), thr, attn_smem>>>(Q, K, V, mask, Ctx);

    // O projection + residual, then LN1
    sgemm_kernel<2><<<gDM, thr>>>(Ctx, Wo, bo, x, T1, TOKENS, DM, DM);
    ln_kernel<<<TOKENS, thr>>>(T1, ln1g, ln1b, A);

    // FFN
    sgemm_kernel<1><<<gFF, thr>>>(A, W1, b1, nullptr, H, TOKENS, DFF, DM);
    sgemm_kernel<2><<<gDM, thr>>>(H, W2, b2, A, T2, TOKENS, DM, DFF);
    ln_kernel<<<TOKENS, thr>>>(T2, ln2g, ln2b, out);
}